// round 14
// baseline (speedup 1.0000x reference)
#include <cuda_runtime.h>
#include <cuda_bf16.h>

// Rotation scan: h_t = lambda * h_{t-1} + x_t  (complex), lambda = r*cos(th) - i*r*sin(th)
// x: (T, N, 2) fp32 -> float2[T][N]. Output same shape.
//
// R14: LDG.128 pressure inside the small-replay-gap class.
// 13-round evidence: wall-vs-kernel gap is ~+13us whenever chip-wide
// front-batched load REQUESTS hit 64K, ~+1..5us at <=32K (request count, not
// bytes: R4's 32K x 16B got gap 0.5). So: NPT=2 channels/thread -> LDG.128,
// 2048 warps x 16 requests = 32K requests carrying 2x the bytes of R1/R7.
// R4 proved this shape; its 110us failure was regs=145 -> 3 CTAs/SM -> two
// ragged waves. Fix: __launch_bounds__(128, 4) caps regs at 128 -> 4 CTAs/SM.
// NB=16 (NL=8 x NPT=2), TT=16, L=16, grid=512, dbl-buffered sagg, plain ld/st.

#define L   16
#define TT  16
#define NL  8              // n-lane threads per time-row
#define NPT 2              // n-channels per thread
#define NB  (NL * NPT)     // 16
#define THREADS (TT * NL)  // 128

__global__ void __launch_bounds__(THREADS, 4)
rot_scan_kernel(const float4* __restrict__ x4,
                const float*  __restrict__ angles,
                const float*  __restrict__ rets,
                float4* __restrict__ out4,
                int T, int N)
{
    const int tid    = threadIdx.x;
    const int n_lane = tid & (NL - 1);
    const int tt     = tid / NL;                  // 0..TT-1
    const int n0     = blockIdx.x * NB + n_lane * NPT;   // first of 2 channels
    const int Nq     = N / NPT;                   // row stride in float4

    const float PI = 3.14159265358979323846f;

    // per-channel operator lambda_c = ret*cos(ang) - i*ret*sin(ang)
    float lr[NPT], li[NPT];
    float plr[NPT], pli[NPT];   // lambda^L
    float wr[NPT],  wi[NPT];    // lambda^(L*tt)
    float flr[NPT], fli[NPT];   // lambda^(L*TT)
#pragma unroll
    for (int c = 0; c < NPT; c++) {
        float ang = (tanhf(angles[n0 + c]) + 1.0f) * 0.5f * PI;
        float ret = (tanhf(rets[n0 + c])   + 1.0f) * 0.5f;
        float sn, cs;
        sincosf(ang, &sn, &cs);
        lr[c] =  ret * cs;
        li[c] = -ret * sn;

        // lambda^L (L=16): 4 squarings
        float ar = lr[c], ai = li[c];
#pragma unroll
        for (int q = 0; q < 4; q++) {
            float nr = ar * ar - ai * ai;
            float ni = 2.0f * ar * ai;
            ar = nr; ai = ni;
        }
        plr[c] = ar; pli[c] = ai;

        // lambda^(L*tt)
        float br = 1.0f, bi = 0.0f;
        for (int j = 0; j < tt; j++) {
            float nr = br * ar - bi * ai;
            float ni = br * ai + bi * ar;
            br = nr; bi = ni;
        }
        wr[c] = br; wi[c] = bi;

        // lambda^(L*TT): 4 more squarings (TT=16)
        float cr = ar, ci = ai;
#pragma unroll
        for (int q = 0; q < 4; q++) {
            float nr = cr * cr - ci * ci;
            float ni = 2.0f * cr * ci;
            cr = nr; ci = ni;
        }
        flr[c] = cr; fli[c] = ci;
    }

    __shared__ float4 sagg[2][TT][NL];   // double buffer -> 1 barrier/iter

    float hpr[NPT] = {0.f, 0.f}, hpi[NPT] = {0.f, 0.f};   // block carry

    float4 v[L];

    const int steps  = L * TT;        // 256
    const int n_iter = T / steps;     // 16

    for (int it = 0; it < n_iter; it++) {
        const int buf = it & 1;
        const int t0  = it * steps + tt * L;
        const float4* xp = x4 + (size_t)t0 * Nq + (n0 >> 1);

        // front-batch 16 independent LDG.128 into v[], then scan in place
#pragma unroll
        for (int i = 0; i < L; i++)
            v[i] = xp[(size_t)i * Nq];

        float br0 = 0.f, bi0 = 0.f, br1 = 0.f, bi1 = 0.f;
#pragma unroll
        for (int i = 0; i < L; i++) {
            float nr0 = fmaf(lr[0], br0, fmaf(-li[0], bi0, v[i].x));
            float ni0 = fmaf(lr[0], bi0, fmaf( li[0], br0, v[i].y));
            float nr1 = fmaf(lr[1], br1, fmaf(-li[1], bi1, v[i].z));
            float ni1 = fmaf(lr[1], bi1, fmaf( li[1], br1, v[i].w));
            br0 = nr0; bi0 = ni0; br1 = nr1; bi1 = ni1;
            v[i] = make_float4(br0, bi0, br1, bi1);
        }
        sagg[buf][tt][n_lane] = make_float4(br0, bi0, br1, bi1);
        __syncthreads();
        // Single-barrier safety: iteration it+2's writes to buffer `buf` are
        // ordered after barrier(it+1), which follows all reads of `buf` in
        // combine(it). Buffers alternate each iteration.

        // combine aggregates: acc_j = lambda^L * acc_{j-1} + A_j
        float ar0 = 0.f, ai0 = 0.f, ar1 = 0.f, ai1 = 0.f;  // running acc
        float cr0 = 0.f, ci0 = 0.f, cr1 = 0.f, ci1 = 0.f;  // carry at j==tt
#pragma unroll
        for (int j = 0; j < TT; j++) {
            if (j == tt) { cr0 = ar0; ci0 = ai0; cr1 = ar1; ci1 = ai1; }
            float4 a = sagg[buf][j][n_lane];
            float nr0 = fmaf(plr[0], ar0, fmaf(-pli[0], ai0, a.x));
            float ni0 = fmaf(plr[0], ai0, fmaf( pli[0], ar0, a.y));
            float nr1 = fmaf(plr[1], ar1, fmaf(-pli[1], ai1, a.z));
            float ni1 = fmaf(plr[1], ai1, fmaf( pli[1], ar1, a.w));
            ar0 = nr0; ai0 = ni0; ar1 = nr1; ai1 = ni1;
        }

        // total carry-in: lambda^(L*tt) * h_prev + I_{tt-1}
        float tr0 = fmaf(wr[0], hpr[0], fmaf(-wi[0], hpi[0], cr0));
        float ti0 = fmaf(wr[0], hpi[0], fmaf( wi[0], hpr[0], ci0));
        float tr1 = fmaf(wr[1], hpr[1], fmaf(-wi[1], hpi[1], cr1));
        float ti1 = fmaf(wr[1], hpi[1], fmaf( wi[1], hpr[1], ci1));

        // outputs: out_i = v_i + lambda^(i+1) * carry
        float4* op = out4 + (size_t)t0 * Nq + (n0 >> 1);
        float qr0 = fmaf(lr[0], tr0, -li[0] * ti0);
        float qi0 = fmaf(lr[0], ti0,  li[0] * tr0);
        float qr1 = fmaf(lr[1], tr1, -li[1] * ti1);
        float qi1 = fmaf(lr[1], ti1,  li[1] * tr1);
#pragma unroll
        for (int i = 0; i < L; i++) {
            float4 o;
            o.x = v[i].x + qr0;
            o.y = v[i].y + qi0;
            o.z = v[i].z + qr1;
            o.w = v[i].w + qi1;
            op[(size_t)i * Nq] = o;
            float nr0 = fmaf(lr[0], qr0, -li[0] * qi0);
            float ni0 = fmaf(lr[0], qi0,  li[0] * qr0);
            float nr1 = fmaf(lr[1], qr1, -li[1] * qi1);
            float ni1 = fmaf(lr[1], qi1,  li[1] * qr1);
            qr0 = nr0; qi0 = ni0; qr1 = nr1; qi1 = ni1;
        }

        // advance block carry: h_prev = lambda^(L*TT) * h_prev + I_{TT-1}
        float nh0r = fmaf(flr[0], hpr[0], fmaf(-fli[0], hpi[0], ar0));
        float nh0i = fmaf(flr[0], hpi[0], fmaf( fli[0], hpr[0], ai0));
        float nh1r = fmaf(flr[1], hpr[1], fmaf(-fli[1], hpi[1], ar1));
        float nh1i = fmaf(flr[1], hpi[1], fmaf( fli[1], hpr[1], ai1));
        hpr[0] = nh0r; hpi[0] = nh0i; hpr[1] = nh1r; hpi[1] = nh1i;
    }
}

extern "C" void kernel_launch(void* const* d_in, const int* in_sizes, int n_in,
                              void* d_out, int out_size)
{
    const float4* x    = (const float4*)d_in[0];
    const float*  angs = (const float*)d_in[1];
    const float*  rts  = (const float*)d_in[2];
    float4* out = (float4*)d_out;

    const int N = in_sizes[1];                       // 8192
    const int T = in_sizes[0] / (2 * N);             // 4096

    const int grid = N / NB;                         // 512 blocks
    rot_scan_kernel<<<grid, THREADS>>>(x, angs, rts, out, T, N);
}

// round 15
// speedup vs baseline: 1.0304x; 1.0304x over previous
#include <cuda_runtime.h>
#include <cuda_bf16.h>

// Rotation scan: h_t = lambda * h_{t-1} + x_t  (complex), lambda = r*cos(th) - i*r*sin(th)
// x: (T, N, 2) fp32 -> float2[T][N]. Output same shape.
//
// R15 = R11 verbatim — the measured-fastest kernel (82.2us, DRAM 74.6%).
// Rationale: after 14 rounds, every config-based theory of the wall-vs-kernel
// gap (block size, store policy, thread count, outstanding-request count:
// falsified by R14's 32K-request/15.8us-gap result) is dead; the gap is
// session-state noise (~+4 or ~+14us, temporally clustered). The only
// controllable term is kernel time, whose optimum is this config:
// NB=16, TT=8, L=32 front-batched loads (high MLP), block=128, grid=512,
// double-buffered sagg (1 barrier/iter), plain ld/st, zero overhead traffic.

#define L   32
#define TT  8
#define NB  16
#define THREADS (TT * NB)   // 128

__global__ void __launch_bounds__(THREADS)
rot_scan_kernel(const float2* __restrict__ x,
                const float*  __restrict__ angles,
                const float*  __restrict__ rets,
                float2* __restrict__ out,
                int T, int N)
{
    const int tid     = threadIdx.x;
    const int n_local = tid & (NB - 1);   // n fastest -> coalesced gmem
    const int tt      = tid / NB;         // 0..TT-1
    const int n       = blockIdx.x * NB + n_local;

    // ---- per-n operator: lambda = ret*cos(ang) - i*ret*sin(ang) ----
    const float PI = 3.14159265358979323846f;
    float ang = (tanhf(angles[n]) + 1.0f) * 0.5f * PI;   // (0, pi)
    float ret = (tanhf(rets[n])   + 1.0f) * 0.5f;        // (0, 1)
    float sn, cs;
    sincosf(ang, &sn, &cs);
    const float lr =  ret * cs;
    const float li = -ret * sn;

    // lambda^L (L=32): 5 complex squarings
    float plr = lr, pli = li;
#pragma unroll
    for (int q = 0; q < 5; q++) {
        float nr = plr * plr - pli * pli;
        float ni = 2.0f * plr * pli;
        plr = nr; pli = ni;
    }
    // lambda^(L*tt): thread-specific weight for block-carry
    float wr = 1.0f, wi = 0.0f;
    for (int j = 0; j < tt; j++) {
        float nr = wr * plr - wi * pli;
        float ni = wr * pli + wi * plr;
        wr = nr; wi = ni;
    }
    // lambda^(L*TT) = (lambda^L)^8: 3 squarings
    float flr = plr, fli = pli;
#pragma unroll
    for (int q = 0; q < 3; q++) {
        float nr = flr * flr - fli * fli;
        float ni = 2.0f * flr * fli;
        flr = nr; fli = ni;
    }

    __shared__ float2 sagg[2][TT][NB];   // double buffer -> 1 barrier/iter

    float hpr = 0.0f, hpi = 0.0f;   // running carry: h before this super-iteration

    float2 v[L];

    const int steps  = L * TT;       // 256
    const int n_iter = T / steps;    // 16

    for (int it = 0; it < n_iter; it++) {
        const int buf = it & 1;
        const int t0  = it * steps + tt * L;
        const float2* xp = x + (size_t)t0 * N + n;

        // load all L values first (independent -> ptxas front-batches LDGs,
        // high MLP), then run the dependent local scan in-place
#pragma unroll
        for (int i = 0; i < L; i++)
            v[i] = xp[(size_t)i * N];

        float br = 0.0f, bi = 0.0f;
#pragma unroll
        for (int i = 0; i < L; i++) {
            float nr = fmaf(lr, br, fmaf(-li, bi, v[i].x));
            float ni = fmaf(lr, bi, fmaf( li, br, v[i].y));
            br = nr; bi = ni;
            v[i].x = br; v[i].y = bi;
        }
        sagg[buf][tt][n_local] = make_float2(br, bi);
        __syncthreads();
        // Single-barrier safety: iteration it+2's writes to buffer `buf` are
        // ordered after barrier(it+1), which follows all reads of `buf` in
        // combine(it). Buffers alternate each iteration.

        // combine aggregates: acc_j = lambda^L * acc_{j-1} + A_j
        // carry for this thread = acc just before adding A_tt (i.e. I_{tt-1})
        float accr = 0.0f, acci = 0.0f;
        float carr = 0.0f, cari = 0.0f;
#pragma unroll
        for (int j = 0; j < TT; j++) {
            if (j == tt) { carr = accr; cari = acci; }
            float2 a = sagg[buf][j][n_local];
            float nr = fmaf(plr, accr, fmaf(-pli, acci, a.x));
            float ni = fmaf(plr, acci, fmaf( pli, accr, a.y));
            accr = nr; acci = ni;
        }

        // total carry-in for this thread = lambda^(L*tt) * h_prev + I_{tt-1}
        float cr = fmaf(wr, hpr, fmaf(-wi, hpi, carr));
        float ci = fmaf(wr, hpi, fmaf( wi, hpr, cari));

        // outputs: out_i = v_i + lambda^(i+1) * carry
        float2* op = out + (size_t)t0 * N + n;
        float qr = fmaf(lr, cr, -li * ci);
        float qi = fmaf(lr, ci,  li * cr);
#pragma unroll
        for (int i = 0; i < L; i++) {
            float2 o;
            o.x = v[i].x + qr;
            o.y = v[i].y + qi;
            op[(size_t)i * N] = o;
            float nr = fmaf(lr, qr, -li * qi);
            float ni = fmaf(lr, qi,  li * qr);
            qr = nr; qi = ni;
        }

        // advance block carry: h_prev = lambda^(L*TT) * h_prev + I_{TT-1}
        float nhr = fmaf(flr, hpr, fmaf(-fli, hpi, accr));
        float nhi = fmaf(flr, hpi, fmaf( fli, hpr, acci));
        hpr = nhr; hpi = nhi;
    }
}

extern "C" void kernel_launch(void* const* d_in, const int* in_sizes, int n_in,
                              void* d_out, int out_size)
{
    const float2* x    = (const float2*)d_in[0];
    const float*  angs = (const float*)d_in[1];
    const float*  rts  = (const float*)d_in[2];
    float2* out = (float2*)d_out;

    const int N = in_sizes[1];                       // 8192
    const int T = in_sizes[0] / (2 * N);             // 4096

    const int grid = N / NB;                         // 512 blocks
    rot_scan_kernel<<<grid, THREADS>>>(x, angs, rts, out, T, N);
}

// round 16
// speedup vs baseline: 1.0760x; 1.0442x over previous
#include <cuda_runtime.h>
#include <cuda_bf16.h>

// Rotation scan: h_t = lambda * h_{t-1} + x_t  (complex), lambda = r*cos(th) - i*r*sin(th)
// x: (T, N, 2) fp32 -> float2[T][N]. Output same shape.
//
// R16 = R11/R15 (measured kernel optimum: 82.2us, DRAM 74.5%) + __ldcs on the
// single-use input stream (the one unconfounded untested lever; evict-first
// reads keep L2 cleaner for the write stream in steady-state replay).
//
// Session model after 15 rounds: wall ~= max(kernel_time, replay_floor(era)),
// where replay_floor drifted ~90 -> ~97us mid-session (sustained-throughput
// throttling invisible to ncu's isolated launch; all config-based gap theories
// falsified). Only controllable term is kernel time; this config minimizes it:
// NB=16, TT=8, L=32 front-batched loads (high MLP), block=128, grid=512,
// double-buffered sagg (1 barrier/iter), plain stores.

#define L   32
#define TT  8
#define NB  16
#define THREADS (TT * NB)   // 128

__global__ void __launch_bounds__(THREADS)
rot_scan_kernel(const float2* __restrict__ x,
                const float*  __restrict__ angles,
                const float*  __restrict__ rets,
                float2* __restrict__ out,
                int T, int N)
{
    const int tid     = threadIdx.x;
    const int n_local = tid & (NB - 1);   // n fastest -> coalesced gmem
    const int tt      = tid / NB;         // 0..TT-1
    const int n       = blockIdx.x * NB + n_local;

    // ---- per-n operator: lambda = ret*cos(ang) - i*ret*sin(ang) ----
    const float PI = 3.14159265358979323846f;
    float ang = (tanhf(angles[n]) + 1.0f) * 0.5f * PI;   // (0, pi)
    float ret = (tanhf(rets[n])   + 1.0f) * 0.5f;        // (0, 1)
    float sn, cs;
    sincosf(ang, &sn, &cs);
    const float lr =  ret * cs;
    const float li = -ret * sn;

    // lambda^L (L=32): 5 complex squarings
    float plr = lr, pli = li;
#pragma unroll
    for (int q = 0; q < 5; q++) {
        float nr = plr * plr - pli * pli;
        float ni = 2.0f * plr * pli;
        plr = nr; pli = ni;
    }
    // lambda^(L*tt): thread-specific weight for block-carry
    float wr = 1.0f, wi = 0.0f;
    for (int j = 0; j < tt; j++) {
        float nr = wr * plr - wi * pli;
        float ni = wr * pli + wi * plr;
        wr = nr; wi = ni;
    }
    // lambda^(L*TT) = (lambda^L)^8: 3 squarings
    float flr = plr, fli = pli;
#pragma unroll
    for (int q = 0; q < 3; q++) {
        float nr = flr * flr - fli * fli;
        float ni = 2.0f * flr * fli;
        flr = nr; fli = ni;
    }

    __shared__ float2 sagg[2][TT][NB];   // double buffer -> 1 barrier/iter

    float hpr = 0.0f, hpi = 0.0f;   // running carry: h before this super-iteration

    float2 v[L];

    const int steps  = L * TT;       // 256
    const int n_iter = T / steps;    // 16

    for (int it = 0; it < n_iter; it++) {
        const int buf = it & 1;
        const int t0  = it * steps + tt * L;
        const float2* xp = x + (size_t)t0 * N + n;

        // load all L values first (independent -> ptxas front-batches LDGs,
        // high MLP); evict-first: x is single-use, keep L2 for the stores
#pragma unroll
        for (int i = 0; i < L; i++)
            v[i] = __ldcs(xp + (size_t)i * N);

        float br = 0.0f, bi = 0.0f;
#pragma unroll
        for (int i = 0; i < L; i++) {
            float nr = fmaf(lr, br, fmaf(-li, bi, v[i].x));
            float ni = fmaf(lr, bi, fmaf( li, br, v[i].y));
            br = nr; bi = ni;
            v[i].x = br; v[i].y = bi;
        }
        sagg[buf][tt][n_local] = make_float2(br, bi);
        __syncthreads();
        // Single-barrier safety: iteration it+2's writes to buffer `buf` are
        // ordered after barrier(it+1), which follows all reads of `buf` in
        // combine(it). Buffers alternate each iteration.

        // combine aggregates: acc_j = lambda^L * acc_{j-1} + A_j
        // carry for this thread = acc just before adding A_tt (i.e. I_{tt-1})
        float accr = 0.0f, acci = 0.0f;
        float carr = 0.0f, cari = 0.0f;
#pragma unroll
        for (int j = 0; j < TT; j++) {
            if (j == tt) { carr = accr; cari = acci; }
            float2 a = sagg[buf][j][n_local];
            float nr = fmaf(plr, accr, fmaf(-pli, acci, a.x));
            float ni = fmaf(plr, acci, fmaf( pli, accr, a.y));
            accr = nr; acci = ni;
        }

        // total carry-in for this thread = lambda^(L*tt) * h_prev + I_{tt-1}
        float cr = fmaf(wr, hpr, fmaf(-wi, hpi, carr));
        float ci = fmaf(wr, hpi, fmaf( wi, hpr, cari));

        // outputs: out_i = v_i + lambda^(i+1) * carry
        float2* op = out + (size_t)t0 * N + n;
        float qr = fmaf(lr, cr, -li * ci);
        float qi = fmaf(lr, ci,  li * cr);
#pragma unroll
        for (int i = 0; i < L; i++) {
            float2 o;
            o.x = v[i].x + qr;
            o.y = v[i].y + qi;
            op[(size_t)i * N] = o;
            float nr = fmaf(lr, qr, -li * qi);
            float ni = fmaf(lr, qi,  li * qr);
            qr = nr; qi = ni;
        }

        // advance block carry: h_prev = lambda^(L*TT) * h_prev + I_{TT-1}
        float nhr = fmaf(flr, hpr, fmaf(-fli, hpi, accr));
        float nhi = fmaf(flr, hpi, fmaf( fli, hpr, acci));
        hpr = nhr; hpi = nhi;
    }
}

extern "C" void kernel_launch(void* const* d_in, const int* in_sizes, int n_in,
                              void* d_out, int out_size)
{
    const float2* x    = (const float2*)d_in[0];
    const float*  angs = (const float*)d_in[1];
    const float*  rts  = (const float*)d_in[2];
    float2* out = (float2*)d_out;

    const int N = in_sizes[1];                       // 8192
    const int T = in_sizes[0] / (2 * N);             // 4096

    const int grid = N / NB;                         // 512 blocks
    rot_scan_kernel<<<grid, THREADS>>>(x, angs, rts, out, T, N);
}